// round 8
// baseline (speedup 1.0000x reference)
#include <cuda_runtime.h>
#include <cuda_fp16.h>
#include <cstdint>

#define B_ 64
#define S_ 2048
#define D_ 512

#define TM 64            // M rows per CTA
#define TK 32            // K per stage tile
#define NKT (D_ / TK)    // 16 k-tiles
#define NSTG 3           // pipeline stages
#define NSCH 8           // context S-chunks

// ---------------- scratch globals ----------------
__device__ float g_wq[B_ * D_];
__device__ float g_scores[B_ * S_];
__device__ float g_stats[2 * B_];
__device__ float g_ctx[NSCH][B_ * D_];
// Wc as fp16 in m16n8k16-fragment order: uint4 index = kb<<11 | kk<<10 | wc<<7 | j2<<5 | lane
__device__ __align__(16) uint4 g_wcH[NKT * 2048];

// ---------------- helpers ----------------
__device__ __forceinline__ float fast_tanh(float x) {
    float xc = fminf(fmaxf(x, -15.f), 15.f);
    float e = __expf(2.f * xc);
    return __fdividef(e - 1.f, e + 1.f);
}
// memory_lengths dtype sniff (int64 vs int32): word[1]==0 iff int64 (LE)
__device__ __forceinline__ int load_len(const void* lens, int b) {
    const int* p32 = (const int*)lens;
    if (p32[1] == 0) return (int)((const long long*)lens)[b];
    return p32[b];
}
__device__ __forceinline__ uint32_t smem_u32(const void* p) {
    uint32_t a;
    asm("{ .reg .u64 t; cvta.to.shared.u64 t, %1; cvt.u32.u64 %0, t; }" : "=r"(a) : "l"(p));
    return a;
}
__device__ __forceinline__ void cp_async16(uint32_t dst, const void* src) {
    asm volatile("cp.async.cg.shared.global [%0], [%1], 16;" :: "r"(dst), "l"(src));
}
__device__ __forceinline__ uint32_t packh2(float a, float b) {
    __half2 h = __floats2half2_rn(a, b);
    return *(uint32_t*)&h;
}
__device__ __forceinline__ void mma_fp16(float* c, const uint32_t* a,
                                         uint32_t b0, uint32_t b1) {
    asm volatile(
        "mma.sync.aligned.m16n8k16.row.col.f32.f16.f16.f32 "
        "{%0,%1,%2,%3}, {%4,%5,%6,%7}, {%8,%9}, {%0,%1,%2,%3};"
        : "+f"(c[0]), "+f"(c[1]), "+f"(c[2]), "+f"(c[3])
        : "r"(a[0]), "r"(a[1]), "r"(a[2]), "r"(a[3]), "r"(b0), "r"(b1));
}

// ============================================================
// Kernel 0: prep Wc -> g_wcH (fp16, m16n8k16 B-fragment order). grid 64, block 512.
// ============================================================
__global__ void prep_wc_kernel(const float* __restrict__ Wc) {
    int p = blockIdx.x * 512 + threadIdx.x;     // 32768 uint4
    int lane = p & 31;
    int j2   = (p >> 5) & 3;
    int wc   = (p >> 7) & 7;
    int kk   = (p >> 10) & 1;
    int kb   = (p >> 11) & 15;
    int g = lane >> 2, t = lane & 3;
    int ne = wc * 64 + j2 * 16 + g;
    int no = ne + 8;
    int k0 = kb * 32 + kk * 16 + 2 * t;
    const float* we = Wc + (size_t)ne * D_;
    const float* wo = Wc + (size_t)no * D_;
    uint4 f;
    f.x = packh2(we[k0],     we[k0 + 1]);
    f.y = packh2(we[k0 + 8], we[k0 + 9]);
    f.z = packh2(wo[k0],     wo[k0 + 1]);
    f.w = packh2(wo[k0 + 8], wo[k0 + 9]);
    g_wcH[p] = f;
}

// ============================================================
// Kernel 1: wq = source @ Wq^T + bq.  grid (4, B), block 128
// ============================================================
__global__ void wq_kernel(const float* __restrict__ src,
                          const float* __restrict__ Wq,
                          const float* __restrict__ bq) {
    int b = blockIdx.y;
    int e = blockIdx.x * 128 + threadIdx.x;
    __shared__ __align__(16) float s_src[D_];
    for (int i = threadIdx.x; i < D_; i += 128) s_src[i] = src[b * D_ + i];
    __syncthreads();
    const float4* w4 = (const float4*)(Wq + (size_t)e * D_);
    const float4* s4 = (const float4*)s_src;
    float acc = 0.f;
#pragma unroll 8
    for (int i = 0; i < D_ / 4; ++i) {
        float4 wv = w4[i], xv = s4[i];
        acc += wv.x * xv.x + wv.y * xv.y + wv.z * xv.z + wv.w * xv.w;
    }
    g_wq[b * D_ + e] = acc + bq[e];
}

// ============================================================
// Kernel 2: fused scores, fp16 m16n8k16, 3-stage cp.async pipeline,
// one barrier per tile. grid (S/64, B), block 512 (2wr x 8wc).
// ============================================================
#define A_U32 1024                  // uint32 per A buffer
#define B_U32 8192                  // uint32 per B buffer
#define OF_AS   0
#define OF_BS   (NSTG * A_U32)
#define OF_WQ   (OF_BS + NSTG * B_U32)
#define OF_V    (OF_WQ + D_)
#define OF_PART (OF_V + D_)
#define SMEM_U32 (OF_PART + TM * 8)
#define SMEM_BYTES (SMEM_U32 * 4)

__global__ void __launch_bounds__(512, 1)
scores_kernel(const float* __restrict__ mb, const float* __restrict__ vvec) {
    extern __shared__ __align__(16) uint32_t sm[];
    uint32_t* As = sm + OF_AS;
    float* swq   = (float*)(sm + OF_WQ);
    float* sv    = (float*)(sm + OF_V);
    float* spart = (float*)(sm + OF_PART);

    const int b   = blockIdx.y;
    const int s0  = blockIdx.x * TM;
    const int tid = threadIdx.x;
    const int wid = tid >> 5, lane = tid & 31;
    const int g = lane >> 2, t = lane & 3;
    const int wr = wid >> 3, wc = wid & 7;
    const int m0 = wr * 32, n0 = wc * 64;

    for (int i = tid; i < D_; i += 512) {
        swq[i] = g_wq[b * D_ + i];
        sv[i]  = vvec[i];
    }

    // A staging: thread -> (row = tid>>3, 4 k at koff=(tid&7)*4) -> 2 fp16x2 stores
    const int am   = tid >> 3;
    const int koff = (tid & 7) * 4;
    const float* a_gbase = mb + (size_t)b * S_ * D_ + (size_t)(s0 + am) * D_ + koff;
    const uint32_t sbase = smem_u32(sm);
    int i0;
    {
        int kk = koff >> 4;
        int tt = (koff & 7) >> 1;
        int kq = (koff & 15) >> 3;
        int gg = am & 7, pm = (am >> 3) & 1, awr = (am >> 5) & 1, mt = (am >> 4) & 1;
        i0 = ((kk * 2 + awr) * 2 + mt) * 128 + (gg * 4 + tt) * 4 + (kq * 2 + pm);
    }

    float acc[2][8][4];
#pragma unroll
    for (int mt = 0; mt < 2; ++mt)
#pragma unroll
        for (int j = 0; j < 8; ++j)
#pragma unroll
            for (int q = 0; q < 4; ++q) acc[mt][j][q] = 0.f;

#define STAGE_B(kb_, buf_) do {                                            \
        const uint4* bsrc4 = g_wcH + (kb_) * 2048;                         \
        uint32_t bdst = sbase + (OF_BS + (buf_) * B_U32) * 4;              \
        _Pragma("unroll")                                                  \
        for (int c = 0; c < 4; ++c) {                                      \
            int fi = tid + c * 512;                                        \
            cp_async16(bdst + fi * 16, bsrc4 + fi);                        \
        }                                                                  \
    } while (0)

    // ---- prologue: stage tiles 0 and 1 ----
    {
        STAGE_B(0, 0);
        asm volatile("cp.async.commit_group;" ::: "memory");
        STAGE_B(1, 1);
        asm volatile("cp.async.commit_group;" ::: "memory");
        float4 a0 = *(const float4*)a_gbase;
        float4 a1 = *(const float4*)(a_gbase + TK);
        As[i0]             = packh2(a0.x, a0.y);
        As[i0 + 4]         = packh2(a0.z, a0.w);
        As[A_U32 + i0]     = packh2(a1.x, a1.y);
        As[A_U32 + i0 + 4] = packh2(a1.z, a1.w);
    }

#pragma unroll 1
    for (int kb = 0; kb < NKT; ++kb) {
        const int cur = kb % NSTG;
        const bool has = (kb + 2) < NKT;

        __syncthreads();   // compute kb-1 done everywhere; buf (kb+2)%3 free; A STS visible

        float4 av;
        if (has) {
            av = *(const float4*)(a_gbase + (kb + 2) * TK);   // LDG early, consumed after MMA
            STAGE_B(kb + 2, (kb + 2) % NSTG);
            asm volatile("cp.async.commit_group;" ::: "memory");
            asm volatile("cp.async.wait_group 2;" ::: "memory");
        } else {
            asm volatile("cp.async.wait_group 0;" ::: "memory");
        }

        const uint32_t* Ac = As + cur * A_U32;
        const uint4* Bc = (const uint4*)(sm + OF_BS + cur * B_U32);
#pragma unroll
        for (int kk = 0; kk < 2; ++kk) {
            uint32_t a[2][4];
#pragma unroll
            for (int mt = 0; mt < 2; ++mt) {
                uint4 af = *(const uint4*)(Ac + ((kk * 2 + wr) * 2 + mt) * 128 + lane * 4);
                a[mt][0] = af.x; a[mt][1] = af.y; a[mt][2] = af.z; a[mt][3] = af.w;
            }
            const uint4* brow = Bc + ((kk * 8 + wc) * 4) * 32 + lane;
#pragma unroll
            for (int j2 = 0; j2 < 4; ++j2) {
                uint4 bf = brow[j2 * 32];
                mma_fp16(acc[0][j2 * 2],     a[0], bf.x, bf.y);
                mma_fp16(acc[1][j2 * 2],     a[1], bf.x, bf.y);
                mma_fp16(acc[0][j2 * 2 + 1], a[0], bf.z, bf.w);
                mma_fp16(acc[1][j2 * 2 + 1], a[1], bf.z, bf.w);
            }
        }

        if (has) {   // A STS after MMA: LDG latency hidden by compute
            uint32_t* Ad = As + ((kb + 2) % NSTG) * A_U32;
            Ad[i0]     = packh2(av.x, av.y);
            Ad[i0 + 4] = packh2(av.z, av.w);
        }
    }

    // ---- epilogue: tanh + v dot, reduce ----
    float p[4] = {0.f, 0.f, 0.f, 0.f};
#pragma unroll
    for (int mt = 0; mt < 2; ++mt)
#pragma unroll
        for (int j = 0; j < 8; ++j) {
            const int c = n0 + j * 8 + 2 * t;
            const float v0 = sv[c], v1 = sv[c + 1];
            const float w0 = swq[c], w1 = swq[c + 1];
            p[mt * 2 + 0] += fast_tanh(w0 + acc[mt][j][0]) * v0 +
                             fast_tanh(w1 + acc[mt][j][1]) * v1;
            p[mt * 2 + 1] += fast_tanh(w0 + acc[mt][j][2]) * v0 +
                             fast_tanh(w1 + acc[mt][j][3]) * v1;
        }
#pragma unroll
    for (int q = 0; q < 4; ++q) {
        p[q] += __shfl_xor_sync(0xFFFFFFFFu, p[q], 1);
        p[q] += __shfl_xor_sync(0xFFFFFFFFu, p[q], 2);
    }
    if (t == 0) {
#pragma unroll
        for (int mt = 0; mt < 2; ++mt) {
            spart[(m0 + mt * 16 + g) * 8 + wc]     = p[mt * 2 + 0];
            spart[(m0 + mt * 16 + g + 8) * 8 + wc] = p[mt * 2 + 1];
        }
    }
    __syncthreads();
    if (tid < TM) {
        float s = 0.f;
#pragma unroll
        for (int w = 0; w < 8; ++w) s += spart[tid * 8 + w];
        g_scores[b * S_ + s0 + tid] = s;
    }
}

// ============================================================
// Kernel 3: masked softmax stats. grid B, block 1024
// ============================================================
__global__ void stats_kernel(const void* __restrict__ lens) {
    __shared__ float red[1024];
    int b = blockIdx.x, tid = threadIdx.x;
    int len = load_len(lens, b);

    float m = -3.4e38f;
    for (int s = tid; s < S_; s += 1024)
        if (s < len) m = fmaxf(m, g_scores[b * S_ + s]);
    red[tid] = m;
    __syncthreads();
    for (int o = 512; o > 0; o >>= 1) {
        if (tid < o) red[tid] = fmaxf(red[tid], red[tid + o]);
        __syncthreads();
    }
    m = red[0];
    __syncthreads();

    float sum = 0.f;
    for (int s = tid; s < S_; s += 1024)
        if (s < len) sum += __expf(g_scores[b * S_ + s] - m);
    red[tid] = sum;
    __syncthreads();
    for (int o = 512; o > 0; o >>= 1) {
        if (tid < o) red[tid] += red[tid + o];
        __syncthreads();
    }
    if (tid == 0) { g_stats[2 * b] = m; g_stats[2 * b + 1] = red[0]; }
}

// ============================================================
// Kernel 4a: context partials. grid (32, B): x = dch(4) + 4*sch(8). block 128
// ============================================================
__global__ void context_part_kernel(const float* __restrict__ mb,
                                    const void* __restrict__ lens,
                                    float* __restrict__ out) {
    __shared__ float w[256];
    int b = blockIdx.y, tid = threadIdx.x;
    int dch = blockIdx.x & 3, sch = blockIdx.x >> 2;
    int len = load_len(lens, b);
    float m = g_stats[2 * b];
    float inv = __fdividef(1.f, g_stats[2 * b + 1]);

    int sbase = sch * 256;
    for (int i = tid; i < 256; i += 128) {
        int s = sbase + i;
        w[i] = (s < len) ? __expf(g_scores[b * S_ + s] - m) * inv : 0.f;
    }
    __syncthreads();

    if (dch == 0) {
        float* align_out = out + B_ * D_;
        for (int i = tid; i < 256; i += 128) align_out[b * S_ + sbase + i] = w[i];
    }

    int d = dch * 128 + tid;
    const float* p = mb + (size_t)b * S_ * D_ + (size_t)sbase * D_ + d;
    float acc = 0.f;
#pragma unroll 8
    for (int i = 0; i < 256; ++i) acc += w[i] * p[(size_t)i * D_];
    g_ctx[sch][b * D_ + d] = acc;
}

// ============================================================
// Kernel 4b: combine context partials. grid B, block 128
// ============================================================
__global__ void combine_kernel(float* __restrict__ out) {
    int b = blockIdx.x, tid = threadIdx.x;
    for (int d = tid; d < D_; d += 128) {
        int i = b * D_ + d;
        float s = 0.f;
#pragma unroll
        for (int c = 0; c < NSCH; ++c) s += g_ctx[c][i];
        out[i] = s;
    }
}

// ============================================================
extern "C" void kernel_launch(void* const* d_in, const int* in_sizes, int n_in,
                              void* d_out, int out_size) {
    const float* source = (const float*)d_in[0];
    const float* mb     = (const float*)d_in[1];
    const void*  lens   = (const void*)d_in[2];
    const float* Wq     = (const float*)d_in[3];
    const float* bq     = (const float*)d_in[4];
    const float* Wc     = (const float*)d_in[5];
    const float* v      = (const float*)d_in[6];
    float*       out    = (float*)d_out;

    cudaFuncSetAttribute(scores_kernel,
                         cudaFuncAttributeMaxDynamicSharedMemorySize, SMEM_BYTES);

    prep_wc_kernel<<<64, 512>>>(Wc);
    wq_kernel<<<dim3(4, B_), 128>>>(source, Wq, bq);
    scores_kernel<<<dim3(S_ / TM, B_), 512, SMEM_BYTES>>>(mb, v);
    stats_kernel<<<B_, 1024>>>(lens);
    context_part_kernel<<<dim3(32, B_), 128>>>(mb, lens, out);
    combine_kernel<<<B_, 128>>>(out);
}